// round 6
// baseline (speedup 1.0000x reference)
#include <cuda_runtime.h>
#include <cuda_fp16.h>
#include <cstdint>

#define NPAT 50000
#define NCON 20000
#define NN   70000
#define EE   800000
#define HH   128
#define LL   2

// ---------------- scratch (static device globals; no allocs allowed) ----------------
__device__ float  g_buf0[(size_t)NN * HH];
__device__ float  g_buf1[(size_t)NN * HH];
__device__ float  g_agg [(size_t)NN * HH];
__device__ __half g_h0  [(size_t)NN * HH];   // fp16 copy of layer-0 input (gather only)
__device__ __half g_h1  [(size_t)NN * HH];   // fp16 copy of layer-1 input (gather only)
__device__ int    g_deg [NN];
__device__ float  g_rcnt[NN];
__device__ int    g_off [NN + 1];
__device__ int    g_cur [NN];
__device__ int    g_csr [2 * EE];
// pre-transposed/split weights: [variant(4)*split(2)][k(256)][n(128)]
__device__ float g_B[(size_t)8 * 256 * 128];

// ---------------- helpers ----------------
__device__ __forceinline__ float cvt_tf32(float v) {
    float h; asm("cvt.rna.tf32.f32 %0, %1;" : "=f"(h) : "f"(v)); return h;
}

__device__ __forceinline__ void mma_tf32(float* c, const uint32_t* a, const uint32_t* b) {
    asm volatile(
        "mma.sync.aligned.m16n8k8.row.col.f32.tf32.tf32.f32 "
        "{%0,%1,%2,%3}, {%4,%5,%6,%7}, {%8,%9}, {%0,%1,%2,%3};"
        : "+f"(c[0]), "+f"(c[1]), "+f"(c[2]), "+f"(c[3])
        : "r"(a[0]), "r"(a[1]), "r"(a[2]), "r"(a[3]),
          "r"(b[0]), "r"(b[1]));
}

// ---------------- degree histogram ----------------
__global__ void deg_kernel(const int* __restrict__ dst_pc, const int* __restrict__ dst_cp,
                           int* __restrict__ deg) {
    int i = blockIdx.x * blockDim.x + threadIdx.x;
    if (i < EE)               atomicAdd(&deg[NPAT + dst_pc[i]], 1);
    else if (i < 2 * EE)      atomicAdd(&deg[dst_cp[i - EE]], 1);
}

// ---------------- single-block exclusive scan (+ rcnt + cur zero) -------------------
__global__ void scan_kernel(const int* __restrict__ deg, int* __restrict__ off,
                            float* __restrict__ rcnt, int* __restrict__ cur) {
    __shared__ int ssum[1024];
    int tid = threadIdx.x;
    const int PER = (NN + 1023) / 1024;
    int base = tid * PER;
    int s = 0;
    for (int i = 0; i < PER; i++) { int idx = base + i; if (idx < NN) s += deg[idx]; }
    ssum[tid] = s;
    __syncthreads();
    for (int ofs = 1; ofs < 1024; ofs <<= 1) {
        int v = (tid >= ofs) ? ssum[tid - ofs] : 0;
        __syncthreads();
        ssum[tid] += v;
        __syncthreads();
    }
    int run = (tid == 0) ? 0 : ssum[tid - 1];
    for (int i = 0; i < PER; i++) {
        int idx = base + i;
        if (idx < NN) {
            int d = deg[idx];
            off[idx] = run; run += d;
            rcnt[idx] = 1.0f / (float)max(d, 1);
            cur[idx] = 0;
        }
    }
    if (tid == 0) off[NN] = ssum[1023];
}

// ---------------- CSR fill ----------------
__global__ void fill_kernel(const int* __restrict__ src_pc, const int* __restrict__ dst_pc,
                            const int* __restrict__ src_cp, const int* __restrict__ dst_cp,
                            const int* __restrict__ off, int* __restrict__ cur,
                            int* __restrict__ csr) {
    int i = blockIdx.x * blockDim.x + threadIdx.x;
    int s, d;
    if (i < EE)          { s = src_pc[i];             d = NPAT + dst_pc[i]; }
    else if (i < 2 * EE) { s = NPAT + src_cp[i - EE]; d = dst_cp[i - EE]; }
    else return;
    int pos = off[d] + atomicAdd(&cur[d], 1);
    csr[pos] = s;
}

// ---------------- fp16 gather-aggregate ----------------
__global__ void gather_h_kernel(const __half* __restrict__ X16,
                                const int* __restrict__ off, const int* __restrict__ csr,
                                const float* __restrict__ rcnt, float* __restrict__ AGG) {
    int warp = (int)((blockIdx.x * (long long)blockDim.x + threadIdx.x) >> 5);
    if (warp >= NN) return;
    int lane = threadIdx.x & 31;
    int beg = off[warp], end = off[warp + 1];
    float4 acc = make_float4(0.f, 0.f, 0.f, 0.f);
    int e = beg;
    for (; e + 32 <= end; e += 32) {
        int idx = csr[e + lane];
#pragma unroll
        for (int j = 0; j < 32; j++) {
            int s = __shfl_sync(0xffffffffu, idx, j);
            uint2 u = ((const uint2*)(X16 + (size_t)s * HH))[lane];
            float2 f0 = __half22float2(*(__half2*)&u.x);
            float2 f1 = __half22float2(*(__half2*)&u.y);
            acc.x += f0.x; acc.y += f0.y; acc.z += f1.x; acc.w += f1.y;
        }
    }
    int rem = end - e;
    if (rem > 0) {
        int idx = (lane < rem) ? csr[e + lane] : 0;
        for (int j = 0; j < rem; j++) {
            int s = __shfl_sync(0xffffffffu, idx, j);
            uint2 u = ((const uint2*)(X16 + (size_t)s * HH))[lane];
            float2 f0 = __half22float2(*(__half2*)&u.x);
            float2 f1 = __half22float2(*(__half2*)&u.y);
            acc.x += f0.x; acc.y += f0.y; acc.z += f1.x; acc.w += f1.y;
        }
    }
    float rc = rcnt[warp];
    ((float4*)(AGG + (size_t)warp * HH))[lane] =
        make_float4(acc.x * rc, acc.y * rc, acc.z * rc, acc.w * rc);
}

// ---------------- input projection (FFMA, round-4) + fp16 copy ----------------------
template <int K>
__global__ void proj_kernel(const float* __restrict__ A, const float* __restrict__ W,
                            const float* __restrict__ bias, float* __restrict__ C,
                            __half* __restrict__ CH, int M) {
    extern __shared__ float sm[];
    float* sW = sm;
    float* sA = sm + K * 128;
    int tid = threadIdx.x;

    float4* sW4 = (float4*)sW;
    const float4* Wg = (const float4*)W;
    for (int i = tid; i < K * 32; i += 256) sW4[i] = Wg[i];
    {
        int row = tid >> 2, q = tid & 3;
        int r = blockIdx.x * 64 + row;
        const int f4p = K / 16;
        float4* dst = (float4*)(sA + row * K) + q * f4p;
        if (r < M) {
            const float4* Ar = (const float4*)(A + (size_t)r * K) + q * f4p;
#pragma unroll
            for (int i = 0; i < f4p; i++) dst[i] = Ar[i];
        } else {
#pragma unroll
            for (int i = 0; i < f4p; i++) dst[i] = make_float4(0.f, 0.f, 0.f, 0.f);
        }
    }
    __syncthreads();

    int rg = tid >> 5, cg = tid & 31;
    float4 acc[8];
#pragma unroll
    for (int i = 0; i < 8; i++) acc[i] = make_float4(0.f, 0.f, 0.f, 0.f);
    const float4* sA4 = (const float4*)sA;
#pragma unroll 2
    for (int k4 = 0; k4 < K / 4; k4++) {
        float4 w0 = sW4[(4 * k4 + 0) * 32 + cg];
        float4 w1 = sW4[(4 * k4 + 1) * 32 + cg];
        float4 w2 = sW4[(4 * k4 + 2) * 32 + cg];
        float4 w3 = sW4[(4 * k4 + 3) * 32 + cg];
#pragma unroll
        for (int i = 0; i < 8; i++) {
            float4 a = sA4[(rg * 8 + i) * (K / 4) + k4];
            acc[i].x += a.x * w0.x + a.y * w1.x + a.z * w2.x + a.w * w3.x;
            acc[i].y += a.x * w0.y + a.y * w1.y + a.z * w2.y + a.w * w3.y;
            acc[i].z += a.x * w0.z + a.y * w1.z + a.z * w2.z + a.w * w3.z;
            acc[i].w += a.x * w0.w + a.y * w1.w + a.z * w2.w + a.w * w3.w;
        }
    }
    float4 bb = ((const float4*)bias)[cg];
#pragma unroll
    for (int i = 0; i < 8; i++) {
        int r = blockIdx.x * 64 + rg * 8 + i;
        if (r < M) {
            float4 v = make_float4(acc[i].x + bb.x, acc[i].y + bb.y,
                                   acc[i].z + bb.z, acc[i].w + bb.w);
            ((float4*)(C + (size_t)r * HH))[cg] = v;
            uint2 h;
            *(__half2*)&h.x = __floats2half2_rn(v.x, v.y);
            *(__half2*)&h.y = __floats2half2_rn(v.z, v.w);
            ((uint2*)(CH + (size_t)r * HH))[cg] = h;
        }
    }
}

// ---------------- weight prep: transpose + tf32-split (round-4 layout) --------------
__global__ void prepB_kernel(const float* __restrict__ W_root, const float* __restrict__ W_rel,
                             float* __restrict__ B) {
    int i = blockIdx.x * blockDim.x + threadIdx.x;
    if (i >= 4 * 256 * 128) return;
    int n = i & 127;
    int k = (i >> 7) & 255;
    int v = i >> 15;
    int l = v >> 1, type = v & 1;
    float val;
    if (k < 128) {
        val = W_root[((size_t)l * 128 + k) * 128 + n];
    } else {
        int rel = (type == 0) ? 1 : 0;
        val = W_rel[(((size_t)l * 2 + rel) * 128 + (k - 128)) * 128 + n];
    }
    float hi = cvt_tf32(val);
    float lo = val - hi;
    B[(((size_t)(v * 2 + 0)) * 256 + k) * 128 + n] = hi;
    B[(((size_t)(v * 2 + 1)) * 256 + k) * 128 + n] = lo;
}

// ---------------- mma.sync tf32 layer (round-4) + optional fp16 copy -----------------
#define ASTR 36
#define BSTR 136
#define SM_AHI 0
#define SM_ALO (128 * ASTR)
#define SM_BHI (2 * 128 * ASTR)
#define SM_BLO (2 * 128 * ASTR + 32 * BSTR)
#define SM_FLOATS (2 * 128 * ASTR + 2 * 32 * BSTR)

template <bool WRITEH>
__global__ void __launch_bounds__(256, 2)
layer_mma_kernel(const float* __restrict__ X, const float* __restrict__ AGG,
                 const float* __restrict__ Bglob, const float* __restrict__ bias,
                 float* __restrict__ C, __half* __restrict__ CH, int layer) {
    extern __shared__ float sm[];
    int tid = threadIdx.x, wid = tid >> 5, lane = tid & 31;
    int warpM = wid & 3, warpN = wid >> 2;

    const int NBP_T = (NPAT + 127) / 128;   // 391
    int bid = blockIdx.x;
    int base, rowlim, v;
    if (bid < NBP_T) { base = bid * 128;                  rowlim = NPAT; v = layer * 2; }
    else             { base = NPAT + (bid - NBP_T) * 128; rowlim = NN;   v = layer * 2 + 1; }

    float acc[2][8][4];
#pragma unroll
    for (int mt = 0; mt < 2; mt++)
#pragma unroll
        for (int nt = 0; nt < 8; nt++)
#pragma unroll
            for (int r = 0; r < 4; r++) acc[mt][nt][r] = 0.f;

    int arow = tid >> 1;
    int node = base + arow;
    bool valid = node < rowlim;
    int f4base = (tid & 1) * 4;

    for (int chunk = 0; chunk < 8; chunk++) {
        const float* src = (chunk < 4)
            ? (X   + (size_t)node * HH + chunk * 32)
            : (AGG + (size_t)node * HH + (chunk - 4) * 32);
#pragma unroll
        for (int i = 0; i < 4; i++) {
            int f4 = f4base + i;
            float4 a = valid ? ((const float4*)src)[f4] : make_float4(0.f, 0.f, 0.f, 0.f);
            float4 hi4, lo4;
            hi4.x = cvt_tf32(a.x); lo4.x = a.x - hi4.x;
            hi4.y = cvt_tf32(a.y); lo4.y = a.y - hi4.y;
            hi4.z = cvt_tf32(a.z); lo4.z = a.z - hi4.z;
            hi4.w = cvt_tf32(a.w); lo4.w = a.w - hi4.w;
            *(float4*)&sm[SM_AHI + arow * ASTR + f4 * 4] = hi4;
            *(float4*)&sm[SM_ALO + arow * ASTR + f4 * 4] = lo4;
        }
        {
            const float4* bh = (const float4*)(Bglob + (((size_t)(v * 2 + 0)) * 256 + chunk * 32) * 128);
            const float4* bl = (const float4*)(Bglob + (((size_t)(v * 2 + 1)) * 256 + chunk * 32) * 128);
#pragma unroll
            for (int i = 0; i < 4; i++) {
                int idx = tid + 256 * i;
                int kk = idx >> 5, n4 = idx & 31;
                *(float4*)&sm[SM_BHI + kk * BSTR + n4 * 4] = bh[idx];
                *(float4*)&sm[SM_BLO + kk * BSTR + n4 * 4] = bl[idx];
            }
        }
        __syncthreads();

#pragma unroll
        for (int k8 = 0; k8 < 4; k8++) {
            int k0 = k8 * 8;
            uint32_t ah[2][4], al[2][4];
#pragma unroll
            for (int mt = 0; mt < 2; mt++) {
                int r0 = warpM * 32 + mt * 16 + (lane >> 2);
                int c0 = k0 + (lane & 3);
                ah[mt][0] = __float_as_uint(sm[SM_AHI + r0 * ASTR + c0]);
                ah[mt][1] = __float_as_uint(sm[SM_AHI + (r0 + 8) * ASTR + c0]);
                ah[mt][2] = __float_as_uint(sm[SM_AHI + r0 * ASTR + c0 + 4]);
                ah[mt][3] = __float_as_uint(sm[SM_AHI + (r0 + 8) * ASTR + c0 + 4]);
                al[mt][0] = __float_as_uint(sm[SM_ALO + r0 * ASTR + c0]);
                al[mt][1] = __float_as_uint(sm[SM_ALO + (r0 + 8) * ASTR + c0]);
                al[mt][2] = __float_as_uint(sm[SM_ALO + r0 * ASTR + c0 + 4]);
                al[mt][3] = __float_as_uint(sm[SM_ALO + (r0 + 8) * ASTR + c0 + 4]);
            }
#pragma unroll
            for (int nt = 0; nt < 8; nt++) {
                int n = warpN * 64 + nt * 8 + (lane >> 2);
                int kr = k0 + (lane & 3);
                uint32_t bh[2], bl[2];
                bh[0] = __float_as_uint(sm[SM_BHI + kr * BSTR + n]);
                bh[1] = __float_as_uint(sm[SM_BHI + (kr + 4) * BSTR + n]);
                bl[0] = __float_as_uint(sm[SM_BLO + kr * BSTR + n]);
                bl[1] = __float_as_uint(sm[SM_BLO + (kr + 4) * BSTR + n]);
#pragma unroll
                for (int mt = 0; mt < 2; mt++) {
                    mma_tf32(acc[mt][nt], ah[mt], bh);
                    mma_tf32(acc[mt][nt], ah[mt], bl);
                    mma_tf32(acc[mt][nt], al[mt], bh);
                }
            }
        }
        __syncthreads();
    }

#pragma unroll
    for (int mt = 0; mt < 2; mt++) {
        int row = base + warpM * 32 + mt * 16 + (lane >> 2);
#pragma unroll
        for (int nt = 0; nt < 8; nt++) {
            int col = warpN * 64 + nt * 8 + (lane & 3) * 2;
            float2 bv = *(const float2*)&bias[col];
            if (row < rowlim) {
                float2 o;
                o.x = fmaxf(acc[mt][nt][0] + bv.x, 0.f);
                o.y = fmaxf(acc[mt][nt][1] + bv.y, 0.f);
                *(float2*)&C[(size_t)row * HH + col] = o;
                if (WRITEH)
                    *(__half2*)&CH[(size_t)row * HH + col] = __floats2half2_rn(o.x, o.y);
            }
            if (row + 8 < rowlim) {
                float2 o;
                o.x = fmaxf(acc[mt][nt][2] + bv.x, 0.f);
                o.y = fmaxf(acc[mt][nt][3] + bv.y, 0.f);
                *(float2*)&C[(size_t)(row + 8) * HH + col] = o;
                if (WRITEH)
                    *(__half2*)&CH[(size_t)(row + 8) * HH + col] = __floats2half2_rn(o.x, o.y);
            }
        }
    }
}

// ---------------- launch ----------------
extern "C" void kernel_launch(void* const* d_in, const int* in_sizes, int n_in,
                              void* d_out, int out_size) {
    const float* x_patient = (const float*)d_in[0];
    const float* x_concept = (const float*)d_in[1];
    const float* W_p    = (const float*)d_in[2];
    const float* b_p    = (const float*)d_in[3];
    const float* W_c    = (const float*)d_in[4];
    const float* b_c    = (const float*)d_in[5];
    const float* W_root = (const float*)d_in[6];
    const float* b_root = (const float*)d_in[7];
    const float* W_rel  = (const float*)d_in[8];
    const int* src_pc = (const int*)d_in[9];
    const int* dst_pc = (const int*)d_in[10];
    const int* src_cp = (const int*)d_in[11];
    const int* dst_cp = (const int*)d_in[12];
    float* out = (float*)d_out;

    float *buf0, *buf1, *agg, *rcnt, *Bg;
    __half *h0, *h1;
    int *deg, *off, *cur, *csr;
    cudaGetSymbolAddress((void**)&buf0, g_buf0);
    cudaGetSymbolAddress((void**)&buf1, g_buf1);
    cudaGetSymbolAddress((void**)&agg,  g_agg);
    cudaGetSymbolAddress((void**)&h0,   g_h0);
    cudaGetSymbolAddress((void**)&h1,   g_h1);
    cudaGetSymbolAddress((void**)&rcnt, g_rcnt);
    cudaGetSymbolAddress((void**)&deg,  g_deg);
    cudaGetSymbolAddress((void**)&off,  g_off);
    cudaGetSymbolAddress((void**)&cur,  g_cur);
    cudaGetSymbolAddress((void**)&csr,  g_csr);
    cudaGetSymbolAddress((void**)&Bg,   g_B);

    const int PROJ64_SMEM  = (64  * 128 + 64 * 64 ) * 4;
    const int PROJ128_SMEM = (128 * 128 + 64 * 128) * 4;
    const int LAYER_SMEM   = SM_FLOATS * 4;
    cudaFuncSetAttribute(proj_kernel<64>,  cudaFuncAttributeMaxDynamicSharedMemorySize, PROJ64_SMEM);
    cudaFuncSetAttribute(proj_kernel<128>, cudaFuncAttributeMaxDynamicSharedMemorySize, PROJ128_SMEM);
    cudaFuncSetAttribute(layer_mma_kernel<true>,  cudaFuncAttributeMaxDynamicSharedMemorySize, LAYER_SMEM);
    cudaFuncSetAttribute(layer_mma_kernel<false>, cudaFuncAttributeMaxDynamicSharedMemorySize, LAYER_SMEM);

    // ---- CSR build ----
    cudaMemsetAsync(deg, 0, NN * sizeof(int));
    deg_kernel<<<(2 * EE + 255) / 256, 256>>>(dst_pc, dst_cp, deg);
    scan_kernel<<<1, 1024>>>(deg, off, rcnt, cur);
    fill_kernel<<<(2 * EE + 255) / 256, 256>>>(src_pc, dst_pc, src_cp, dst_cp, off, cur, csr);

    // ---- weight prep ----
    prepB_kernel<<<(4 * 256 * 128 + 255) / 256, 256>>>(W_root, W_rel, Bg);

    // ---- projections (FFMA, round-4) + fp16 copy ----
    proj_kernel<64><<<(NPAT + 63) / 64, 256, PROJ64_SMEM>>>(x_patient, W_p, b_p, buf0, h0, NPAT);
    proj_kernel<128><<<(NCON + 63) / 64, 256, PROJ128_SMEM>>>(x_concept, W_c, b_c,
        buf0 + (size_t)NPAT * HH, h0 + (size_t)NPAT * HH, NCON);

    const int NB_TC = (NPAT + 127) / 128 + (NCON + 127) / 128;  // 548
    const int GATHER_BLOCKS = (NN + 7) / 8;

    // ---- layer 0 ----
    gather_h_kernel<<<GATHER_BLOCKS, 256>>>(h0, off, csr, rcnt, agg);
    layer_mma_kernel<true><<<NB_TC, 256, LAYER_SMEM>>>(buf0, agg, Bg, b_root, buf1, h1, 0);

    // ---- layer 1 ----
    gather_h_kernel<<<GATHER_BLOCKS, 256>>>(h1, off, csr, rcnt, agg);
    layer_mma_kernel<false><<<NB_TC, 256, LAYER_SMEM>>>(buf1, agg, Bg, b_root + HH, out,
                                                        (__half*)nullptr, 1);
}